// round 6
// baseline (speedup 1.0000x reference)
#include <cuda_runtime.h>
#include <cuda_fp16.h>
#include <math.h>
#include <stdint.h>

#define NBATCH 4
#define HH 128
#define WWW 128
#define CC 512
#define NN 16384
#define NHEADS 8
#define DHEAD 64
#define MTOT (NBATCH*NN)

// ---------------- scratch ---------------------------------------------------
__device__ __half g_xh[MTOT*CC];         // modulated x, half
__device__ __half g_vh[MTOT*CC];         // v_inp*illu, half
__device__ __half g_q [MTOT*CC];
__device__ __half g_k [MTOT*CC];
__device__ float  g_vi[MTOT*CC];         // v_inp fp32 (PE branch needs it)
__device__ float  g_tmp[NBATCH*2048];
__device__ float  g_cdp[NBATCH*1024];
__device__ float  g_gram[NBATCH*NHEADS*64*64];
__device__ float  g_ssq[NBATCH*NHEADS*64];
__device__ float  g_ssk[NBATCH*NHEADS*64];
__device__ float  g_attn[NBATCH*NHEADS*64*64];
__device__ __half g_wt[3*CC*CC];         // transposed wq,wk,wv  [n][k]
__device__ __half g_wfoldt[NBATCH*CC*CC];// transposed folded proj [b][n][k]

// ---------------- zero accumulators -----------------------------------------
__global__ void zero_small_k() {
    int i = blockIdx.x*blockDim.x + threadIdx.x;
    if (i < NBATCH*NHEADS*64*64) g_gram[i] = 0.f;
    if (i < NBATCH*NHEADS*64) { g_ssq[i] = 0.f; g_ssk[i] = 0.f; }
}

// ---------------- tiny dense (cdp chain) ------------------------------------
__global__ void small_gemm_k(const float* __restrict__ A, const float* __restrict__ Wm,
                             float* __restrict__ out, int K, int Nc) {
    int idx = blockIdx.x*blockDim.x + threadIdx.x;
    if (idx >= NBATCH*Nc) return;
    int b = idx / Nc, j = idx - b*Nc;
    const float* a = A + b*K;
    float acc = 0.f;
    for (int k = 0; k < K; ++k) acc = fmaf(a[k], Wm[k*Nc + j], acc);
    out[idx] = acc;
}

// ---------------- 3x transpose 512x512 -> half (one launch) ------------------
__global__ void transp3_k(const float* __restrict__ w0, const float* __restrict__ w1,
                          const float* __restrict__ w2, __half* __restrict__ Wt) {
    const float* W = (blockIdx.z == 0) ? w0 : (blockIdx.z == 1) ? w1 : w2;
    __half* dst = Wt + (size_t)blockIdx.z * 262144;
    __shared__ float t[32][33];
    int x0 = blockIdx.x*32, y0 = blockIdx.y*32;
    int tx = threadIdx.x, ty = threadIdx.y;
    #pragma unroll
    for (int i = 0; i < 4; ++i)
        t[ty + i*8][tx] = W[(size_t)(y0 + ty + i*8)*512 + x0 + tx];
    __syncthreads();
    #pragma unroll
    for (int i = 0; i < 4; ++i)
        dst[(size_t)(x0 + ty + i*8)*512 + y0 + tx] = __float2half_rn(t[tx][ty + i*8]);
}

// ---------------- xm = x*cdp1+cdp2 -> half -----------------------------------
__global__ void modulate_k(const float* __restrict__ x) {
    long long i = (long long)blockIdx.x*blockDim.x + threadIdx.x;
    long long e = i*4;
    int c = (int)(e & (CC-1));
    int b = (int)(e >> 23);
    float4 xv = ((const float4*)x)[i];
    float4 s = *(const float4*)&g_cdp[b*1024 + c];
    float4 t = *(const float4*)&g_cdp[b*1024 + 512 + c];
    __half2 h0 = __floats2half2_rn(fmaf(xv.x, s.x, t.x), fmaf(xv.y, s.y, t.y));
    __half2 h1 = __floats2half2_rn(fmaf(xv.z, s.z, t.z), fmaf(xv.w, s.w, t.w));
    ((__half2*)g_xh)[i*2]   = h0;
    ((__half2*)g_xh)[i*2+1] = h1;
}

// ---------------- fp16 mma.sync GEMM with ldmatrix ---------------------------
#define KPADH 40
#define HBUF (128*KPADH)
#define GEMM_SMEM (4*HBUF*2)                  // 40960 bytes

__device__ __forceinline__ void mma_f16(
    float& d0, float& d1, float& d2, float& d3,
    uint32_t a0, uint32_t a1, uint32_t a2, uint32_t a3, uint32_t b0, uint32_t b1)
{
    asm volatile(
        "mma.sync.aligned.m16n8k16.row.col.f32.f16.f16.f32 "
        "{%0,%1,%2,%3}, {%4,%5,%6,%7}, {%8,%9}, {%0,%1,%2,%3};"
        : "+f"(d0), "+f"(d1), "+f"(d2), "+f"(d3)
        : "r"(a0), "r"(a1), "r"(a2), "r"(a3), "r"(b0), "r"(b1));
}
__device__ __forceinline__ void ldsm_x4(uint32_t& r0, uint32_t& r1, uint32_t& r2,
                                        uint32_t& r3, uint32_t addr) {
    asm volatile("ldmatrix.sync.aligned.m8n8.x4.shared.b16 {%0,%1,%2,%3}, [%4];"
                 : "=r"(r0), "=r"(r1), "=r"(r2), "=r"(r3) : "r"(addr));
}

// NW=3: q,k (half out) + v (fp32 out + fused vh=v*illu half).  NW=1: final proj.
template<int NW, bool PERB, bool BIAS>
__global__ __launch_bounds__(256)
void gemm_h_k(const __half* __restrict__ A, const __half* __restrict__ WtB,
              const float* __restrict__ bias, const float* __restrict__ illu,
              void* __restrict__ C0, void* __restrict__ C1, void* __restrict__ C2)
{
    extern __shared__ __align__(16) __half smem[];
    int tid = threadIdx.x;
    int wid = tid >> 5, lane = tid & 31;
    int g = lane >> 2, t = lane & 3;
    int wm = wid & 1, wn = wid >> 1;

    int widx  = blockIdx.x >> 2;
    int ntile = blockIdx.x & 3;
    int n0 = ntile * 128;
    int m0 = blockIdx.y * 128;
    int batch = m0 >> 14;

    const __half* Wp = WtB + (size_t)widx*262144 + (PERB ? (size_t)batch*262144 : 0)
                     + (size_t)n0*512;
    bool outhalf = (NW == 3 && widx < 2);
    void* Cout = (NW == 1) ? C0 : ((widx == 0) ? C0 : (widx == 1) ? C1 : C2);

    __half* As[2] = { smem,          smem + HBUF };
    __half* Bs[2] = { smem + 2*HBUF, smem + 3*HBUF };
    uint32_t asm_base[2], bsm_base[2];
    #pragma unroll
    for (int s = 0; s < 2; ++s) {
        asm_base[s] = (uint32_t)__cvta_generic_to_shared(As[s]);
        bsm_base[s] = (uint32_t)__cvta_generic_to_shared(Bs[s]);
    }
    // lane offsets for ldmatrix (bytes)
    uint32_t laneA = (uint32_t)(((lane & 15)*KPADH + ((lane >> 4) << 3)) * 2);
    uint32_t laneB = (uint32_t)(((((lane >> 4) << 3) + (lane & 7))*KPADH + (lane & 8)) * 2);

    float acc[4][4][4];
    #pragma unroll
    for (int i = 0; i < 4; ++i)
        #pragma unroll
        for (int j = 0; j < 4; ++j)
            #pragma unroll
            for (int q = 0; q < 4; ++q) acc[i][j][q] = 0.f;

    auto cpStage = [&](int kt, int buf) {
        #pragma unroll
        for (int j = 0; j < 2; ++j) {
            int f = j*256 + tid;
            int row = f >> 2, c8 = f & 3;
            const __half* srcA = A + (size_t)(m0 + row)*512 + kt*32 + c8*8;
            __half* dA = As[buf] + row*KPADH + c8*8;
            asm volatile("cp.async.cg.shared.global [%0], [%1], 16;"
                :: "l"((uint64_t)__cvta_generic_to_shared(dA)), "l"(srcA) : "memory");
            const __half* srcB = Wp + (size_t)row*512 + kt*32 + c8*8;
            __half* dB = Bs[buf] + row*KPADH + c8*8;
            asm volatile("cp.async.cg.shared.global [%0], [%1], 16;"
                :: "l"((uint64_t)__cvta_generic_to_shared(dB)), "l"(srcB) : "memory");
        }
        asm volatile("cp.async.commit_group;" ::: "memory");
    };

    cpStage(0, 0);

    for (int kt = 0; kt < 16; ++kt) {
        int buf = kt & 1;
        if (kt + 1 < 16) {
            cpStage(kt + 1, buf ^ 1);
            asm volatile("cp.async.wait_group 1;" ::: "memory");
        } else {
            asm volatile("cp.async.wait_group 0;" ::: "memory");
        }
        __syncthreads();

        uint32_t ab = asm_base[buf] + (uint32_t)(wm*64*KPADH*2) + laneA;
        uint32_t bb = bsm_base[buf] + (uint32_t)(wn*32*KPADH*2) + laneB;
        #pragma unroll
        for (int kk = 0; kk < 2; ++kk) {
            uint32_t af[4][4], bf[4][2];
            #pragma unroll
            for (int mt = 0; mt < 4; ++mt)
                ldsm_x4(af[mt][0], af[mt][1], af[mt][2], af[mt][3],
                        ab + (uint32_t)(mt*16*KPADH*2 + kk*32));
            #pragma unroll
            for (int np = 0; np < 2; ++np)
                ldsm_x4(bf[np*2][0], bf[np*2][1], bf[np*2+1][0], bf[np*2+1][1],
                        bb + (uint32_t)(np*16*KPADH*2 + kk*32));
            #pragma unroll
            for (int mt = 0; mt < 4; ++mt)
                #pragma unroll
                for (int nt = 0; nt < 4; ++nt)
                    mma_f16(acc[mt][nt][0], acc[mt][nt][1],
                            acc[mt][nt][2], acc[mt][nt][3],
                            af[mt][0], af[mt][1], af[mt][2], af[mt][3],
                            bf[nt][0], bf[nt][1]);
        }
        __syncthreads();
    }

    // ---- epilogue ----
    #pragma unroll
    for (int mt = 0; mt < 4; ++mt) {
        int r0 = m0 + wm*64 + mt*16 + g;
        #pragma unroll
        for (int nt = 0; nt < 4; ++nt) {
            int col = n0 + wn*32 + nt*8 + 2*t;
            if (outhalf) {
                __half2 h0 = __floats2half2_rn(acc[mt][nt][0], acc[mt][nt][1]);
                __half2 h1 = __floats2half2_rn(acc[mt][nt][2], acc[mt][nt][3]);
                *(__half2*)((__half*)Cout + (size_t)r0*512 + col)     = h0;
                *(__half2*)((__half*)Cout + (size_t)(r0+8)*512 + col) = h1;
            } else {
                float bx = 0.f, by = 0.f;
                if (BIAS) { bx = bias[col]; by = bias[col + 1]; }
                float2 v0 = { acc[mt][nt][0] + bx, acc[mt][nt][1] + by };
                float2 v1 = { acc[mt][nt][2] + bx, acc[mt][nt][3] + by };
                *(float2*)((float*)Cout + (size_t)r0*512 + col)     = v0;
                *(float2*)((float*)Cout + (size_t)(r0+8)*512 + col) = v1;
                if (NW == 3) {  // v output: also vh = v * illu (half)
                    float2 i0 = *(const float2*)(illu + (size_t)r0*512 + col);
                    float2 i1 = *(const float2*)(illu + (size_t)(r0+8)*512 + col);
                    __half2 h0 = __floats2half2_rn(v0.x*i0.x, v0.y*i0.y);
                    __half2 h1 = __floats2half2_rn(v1.x*i1.x, v1.y*i1.y);
                    *(__half2*)(g_vh + (size_t)r0*512 + col)     = h0;
                    *(__half2*)(g_vh + (size_t)(r0+8)*512 + col) = h1;
                }
            }
        }
    }
}

// ---------------- Gram + column norms (half inputs) --------------------------
__global__ __launch_bounds__(256) void gram_k() {
    int bh = blockIdx.x >> 3;
    int chunk = blockIdx.x & 7;
    int b = bh >> 3, h = bh & 7;
    int tid = threadIdx.x;
    __shared__ float qs[4][64], ks[4][64];
    float acc[4][4] = {{0.f}};
    float sq = 0.f, sk = 0.f;
    int ti = tid >> 4, tj = tid & 15;
    const __half* qbase = g_q + (size_t)b*NN*512 + h*64;
    const __half* kbase = g_k + (size_t)b*NN*512 + h*64;
    int n0 = chunk * 2048;
    int lnn = tid >> 5 & 3, lj = (tid & 31) * 2;
    bool isq = tid < 128;
    for (int n = n0; n < n0 + 2048; n += 4) {
        __syncthreads();
        {
            const __half* src = isq ? qbase : kbase;
            __half2 hv = *(const __half2*)(src + (size_t)(n + lnn)*512 + lj);
            float2 fv = __half22float2(hv);
            float* dst = isq ? &qs[lnn][lj] : &ks[lnn][lj];
            dst[0] = fv.x; dst[1] = fv.y;
        }
        __syncthreads();
        #pragma unroll
        for (int nn = 0; nn < 4; ++nn) {
            float kv[4], qv[4];
            #pragma unroll
            for (int ii = 0; ii < 4; ++ii) kv[ii] = ks[nn][ti*4+ii];
            #pragma unroll
            for (int jj = 0; jj < 4; ++jj) qv[jj] = qs[nn][tj*4+jj];
            #pragma unroll
            for (int ii = 0; ii < 4; ++ii)
                #pragma unroll
                for (int jj = 0; jj < 4; ++jj)
                    acc[ii][jj] = fmaf(kv[ii], qv[jj], acc[ii][jj]);
        }
        if (tid < 64) {
            #pragma unroll
            for (int nn = 0; nn < 4; ++nn) sq = fmaf(qs[nn][tid], qs[nn][tid], sq);
        } else if (tid < 128) {
            #pragma unroll
            for (int nn = 0; nn < 4; ++nn) sk = fmaf(ks[nn][tid-64], ks[nn][tid-64], sk);
        }
    }
    float* gp = g_gram + (size_t)bh*4096;
    #pragma unroll
    for (int ii = 0; ii < 4; ++ii)
        #pragma unroll
        for (int jj = 0; jj < 4; ++jj)
            atomicAdd(&gp[(ti*4+ii)*64 + tj*4+jj], acc[ii][jj]);
    if (tid < 64) atomicAdd(&g_ssq[bh*64 + tid], sq);
    else if (tid < 128) atomicAdd(&g_ssk[bh*64 + tid - 64], sk);
}

// ---------------- softmax ----------------------------------------------------
__global__ void softmax_k(const float* __restrict__ rescale) {
    int bh = blockIdx.x;
    int h = bh & 7;
    int i = threadIdx.x;
    __shared__ float rq[64];
    rq[i] = 1.f / fmaxf(sqrtf(g_ssq[bh*64 + i]), 1e-12f);
    __syncthreads();
    float rk = 1.f / fmaxf(sqrtf(g_ssk[bh*64 + i]), 1e-12f);
    float rs = rescale[h];
    const float* gp = g_gram + (size_t)bh*4096 + i*64;
    float vals[64];
    float mx = -1e30f;
    #pragma unroll
    for (int j = 0; j < 64; ++j) {
        vals[j] = gp[j] * rk * rq[j] * rs;
        mx = fmaxf(mx, vals[j]);
    }
    float s = 0.f;
    #pragma unroll
    for (int j = 0; j < 64; ++j) { vals[j] = expf(vals[j] - mx); s += vals[j]; }
    float inv = 1.f / s;
    float* ap = g_attn + (size_t)bh*4096 + i*64;
    #pragma unroll
    for (int j = 0; j < 64; ++j) ap[j] = vals[j] * inv;
}

// ------- fold attn into wproj, TRANSPOSED half output ------------------------
__global__ __launch_bounds__(512) void fold_kT(const float* __restrict__ wproj) {
    int b = blockIdx.x >> 3, h = blockIdx.x & 7;
    int o = threadIdx.x;
    __shared__ float sa[64*64];
    const float* ap = g_attn + (size_t)(b*8 + h)*4096;
    for (int l = o; l < 4096; l += 512) sa[l] = ap[l];
    __syncthreads();
    float wp[64];
    #pragma unroll
    for (int i = 0; i < 64; ++i) wp[i] = wproj[(h*64 + i)*512 + o];
    __half* dst = g_wfoldt + (size_t)b*262144 + (size_t)o*512 + h*64;
    #pragma unroll 4
    for (int j = 0; j < 64; ++j) {
        float acc = 0.f;
        #pragma unroll
        for (int i = 0; i < 64; ++i) acc = fmaf(sa[i*64 + j], wp[i], acc);
        dst[j] = __float2half_rn(acc);
    }
}

// ---------------- fused double 3x3 depthwise conv + gelu, NHWC ---------------
// one block: 8x8 output tile x 64 channels. vi halo 12x12, pe tile 10x10 (smem).
#define DW_SMEM ((144+100)*64*4)
__global__ __launch_bounds__(256) void dwconv_fused_k(const float* __restrict__ vi,
                                                      const float* __restrict__ w1g,
                                                      const float* __restrict__ w2g,
                                                      float* __restrict__ out) {
    extern __shared__ float sm[];
    float* vt = sm;              // 144*64
    float* pt = sm + 144*64;     // 100*64
    int bz = blockIdx.z;
    int b = bz >> 3;
    int c0 = (bz & 7) * 64;
    int y0 = blockIdx.y * 8, x0 = blockIdx.x * 8;
    int tid = threadIdx.x;
    int c = tid & 63;
    int pg = tid >> 6;
    for (int p = pg; p < 144; p += 4) {
        int gy = y0 - 2 + p/12, gx = x0 - 2 + p%12;
        float v = 0.f;
        if (gy >= 0 && gy < HH && gx >= 0 && gx < WWW)
            v = vi[((size_t)(b*HH + gy)*WWW + gx)*CC + c0 + c];
        vt[p*64 + c] = v;
    }
    float w1[9], w2[9];
    #pragma unroll
    for (int t = 0; t < 9; ++t) {
        w1[t] = w1g[(c0 + c)*9 + t];
        w2[t] = w2g[(c0 + c)*9 + t];
    }
    __syncthreads();
    for (int p = pg; p < 100; p += 4) {
        int py = p/10, px = p%10;
        int gy = y0 - 1 + py, gx = x0 - 1 + px;
        float acc = 0.f;
        #pragma unroll
        for (int dy = 0; dy < 3; ++dy)
            #pragma unroll
            for (int dx = 0; dx < 3; ++dx)
                acc = fmaf(vt[((py+dy)*12 + px+dx)*64 + c], w1[dy*3+dx], acc);
        acc = 0.5f*acc*(1.f + erff(acc*0.70710678118654752f));
        if (gy < 0 || gy >= HH || gx < 0 || gx >= WWW) acc = 0.f;  // conv2 zero-pad
        pt[p*64 + c] = acc;
    }
    __syncthreads();
    for (int p = pg; p < 64; p += 4) {
        int oy = p >> 3, ox = p & 7;
        float acc = 0.f;
        #pragma unroll
        for (int dy = 0; dy < 3; ++dy)
            #pragma unroll
            for (int dx = 0; dx < 3; ++dx)
                acc = fmaf(pt[((oy+dy)*10 + ox+dx)*64 + c], w2[dy*3+dx], acc);
        out[((size_t)(b*HH + y0+oy)*WWW + x0+ox)*CC + c0 + c] += acc;
    }
}

// ---------------------------------------------------------------------------
extern "C" void kernel_launch(void* const* d_in, const int* in_sizes, int n_in,
                              void* d_out, int out_size) {
    const float* x_in    = (const float*)d_in[0];
    const float* illu    = (const float*)d_in[1];
    const float* prior   = (const float*)d_in[2];
    const float* wq      = (const float*)d_in[3];
    const float* wk      = (const float*)d_in[4];
    const float* wv      = (const float*)d_in[5];
    const float* rescale = (const float*)d_in[6];
    const float* wproj   = (const float*)d_in[7];
    const float* bproj   = (const float*)d_in[8];
    const float* cw1     = (const float*)d_in[9];
    const float* cw2     = (const float*)d_in[10];
    const float* pw1     = (const float*)d_in[11];
    const float* pw2     = (const float*)d_in[12];
    float* out = (float*)d_out;

    float *p_vi, *p_tmp, *p_cdp;
    __half *p_xh, *p_vh, *p_q, *p_k, *p_wt, *p_wfoldt;
    cudaGetSymbolAddress((void**)&p_xh,     g_xh);
    cudaGetSymbolAddress((void**)&p_vh,     g_vh);
    cudaGetSymbolAddress((void**)&p_q,      g_q);
    cudaGetSymbolAddress((void**)&p_k,      g_k);
    cudaGetSymbolAddress((void**)&p_vi,     g_vi);
    cudaGetSymbolAddress((void**)&p_tmp,    g_tmp);
    cudaGetSymbolAddress((void**)&p_cdp,    g_cdp);
    cudaGetSymbolAddress((void**)&p_wt,     g_wt);
    cudaGetSymbolAddress((void**)&p_wfoldt, g_wfoldt);

    cudaFuncSetAttribute(gemm_h_k<3,false,false>,
                         cudaFuncAttributeMaxDynamicSharedMemorySize, GEMM_SMEM);
    cudaFuncSetAttribute(gemm_h_k<1,true,true>,
                         cudaFuncAttributeMaxDynamicSharedMemorySize, GEMM_SMEM);
    cudaFuncSetAttribute(dwconv_fused_k,
                         cudaFuncAttributeMaxDynamicSharedMemorySize, DW_SMEM);

    // launches 1-5
    zero_small_k<<<512, 256>>>();
    small_gemm_k<<<(NBATCH*2048 + 255)/256, 256>>>(prior, cw1, p_tmp, 512, 2048);
    small_gemm_k<<<(NBATCH*1024 + 255)/256, 256>>>(p_tmp, cw2, p_cdp, 2048, 1024);
    dim3 tb(32, 8), tg(16, 16, 3);
    transp3_k<<<tg, tb>>>(wq, wk, wv, p_wt);
    modulate_k<<<(MTOT*CC/4 + 255)/256, 256>>>(x_in);

    // launch 6 (profiled): q,k (half) + v (fp32) + vh=v*illu (half fused)
    dim3 gq(12, 512);
    gemm_h_k<3,false,false><<<gq, 256, GEMM_SMEM>>>(
        p_xh, p_wt, nullptr, illu, p_q, p_k, p_vi);

    gram_k<<<256, 256>>>();
    softmax_k<<<32, 64>>>(rescale);
    fold_kT<<<32, 512>>>(wproj);

    // out_c = vh @ Wfold_b + bproj
    dim3 gf(4, 512);
    gemm_h_k<1,true,true><<<gf, 256, GEMM_SMEM>>>(
        p_vh, p_wfoldt, bproj, nullptr, out, out, out);

    // PE branch fused: out += dwconv2(gelu(dwconv1(v_inp)))
    dim3 cg(WWW/8, HH/8, NBATCH*8);
    dwconv_fused_k<<<cg, 256, DW_SMEM>>>(p_vi, pw1, pw2, out);
}

// round 11
// speedup vs baseline: 1.0989x; 1.0989x over previous
#include <cuda_runtime.h>
#include <cuda_fp16.h>
#include <math.h>
#include <stdint.h>

#define NBATCH 4
#define HH 128
#define WWW 128
#define CC 512
#define NN 16384
#define NHEADS 8
#define DHEAD 64
#define MTOT (NBATCH*NN)

// ---------------- scratch ---------------------------------------------------
__device__ __half g_xh[MTOT*CC];
__device__ __half g_vh[MTOT*CC];
__device__ __half g_q [MTOT*CC];
__device__ __half g_k [MTOT*CC];
__device__ float  g_vi[MTOT*CC];
__device__ float  g_tmp[NBATCH*2048];
__device__ float  g_cdp[NBATCH*1024];
__device__ float  g_gram[NBATCH*NHEADS*64*64];
__device__ float  g_ssq[NBATCH*NHEADS*64];
__device__ float  g_ssk[NBATCH*NHEADS*64];
__device__ float  g_attn[NBATCH*NHEADS*64*64];
__device__ __half g_wt[3*CC*CC];
__device__ __half g_wfoldt[NBATCH*CC*CC];

// ---------------- zero accumulators -----------------------------------------
__global__ void zero_small_k() {
    int i = blockIdx.x*blockDim.x + threadIdx.x;
    if (i < NBATCH*NHEADS*64*64) g_gram[i] = 0.f;
    if (i < NBATCH*NHEADS*64) { g_ssq[i] = 0.f; g_ssk[i] = 0.f; }
}

// ---------------- tiny dense (cdp chain) ------------------------------------
__global__ void small_gemm_k(const float* __restrict__ A, const float* __restrict__ Wm,
                             float* __restrict__ out, int K, int Nc) {
    int idx = blockIdx.x*blockDim.x + threadIdx.x;
    if (idx >= NBATCH*Nc) return;
    int b = idx / Nc, j = idx - b*Nc;
    const float* a = A + b*K;
    float acc = 0.f;
    for (int k = 0; k < K; ++k) acc = fmaf(a[k], Wm[k*Nc + j], acc);
    out[idx] = acc;
}

// ---------------- 3x transpose 512x512 -> half -------------------------------
__global__ void transp3_k(const float* __restrict__ w0, const float* __restrict__ w1,
                          const float* __restrict__ w2, __half* __restrict__ Wt) {
    const float* W = (blockIdx.z == 0) ? w0 : (blockIdx.z == 1) ? w1 : w2;
    __half* dst = Wt + (size_t)blockIdx.z * 262144;
    __shared__ float t[32][33];
    int x0 = blockIdx.x*32, y0 = blockIdx.y*32;
    int tx = threadIdx.x, ty = threadIdx.y;
    #pragma unroll
    for (int i = 0; i < 4; ++i)
        t[ty + i*8][tx] = W[(size_t)(y0 + ty + i*8)*512 + x0 + tx];
    __syncthreads();
    #pragma unroll
    for (int i = 0; i < 4; ++i)
        dst[(size_t)(x0 + ty + i*8)*512 + y0 + tx] = __float2half_rn(t[tx][ty + i*8]);
}

// ---------------- xm = x*cdp1+cdp2 -> half -----------------------------------
__global__ void modulate_k(const float* __restrict__ x) {
    long long i = (long long)blockIdx.x*blockDim.x + threadIdx.x;
    long long e = i*4;
    int c = (int)(e & (CC-1));
    int b = (int)(e >> 23);
    float4 xv = ((const float4*)x)[i];
    float4 s = *(const float4*)&g_cdp[b*1024 + c];
    float4 t = *(const float4*)&g_cdp[b*1024 + 512 + c];
    __half2 h0 = __floats2half2_rn(fmaf(xv.x, s.x, t.x), fmaf(xv.y, s.y, t.y));
    __half2 h1 = __floats2half2_rn(fmaf(xv.z, s.z, t.z), fmaf(xv.w, s.w, t.w));
    ((__half2*)g_xh)[i*2]   = h0;
    ((__half2*)g_xh)[i*2+1] = h1;
}

// ---------------- fp16 mma.sync GEMM, 3-stage pipeline -----------------------
#define KPADH 40
#define HBUF (128*KPADH)
#define GEMM_SMEM (6*HBUF*2)                 // 3 stages x (A+B) = 61440 bytes

__device__ __forceinline__ void mma_f16(
    float& d0, float& d1, float& d2, float& d3,
    uint32_t a0, uint32_t a1, uint32_t a2, uint32_t a3, uint32_t b0, uint32_t b1)
{
    asm volatile(
        "mma.sync.aligned.m16n8k16.row.col.f32.f16.f16.f32 "
        "{%0,%1,%2,%3}, {%4,%5,%6,%7}, {%8,%9}, {%0,%1,%2,%3};"
        : "+f"(d0), "+f"(d1), "+f"(d2), "+f"(d3)
        : "r"(a0), "r"(a1), "r"(a2), "r"(a3), "r"(b0), "r"(b1));
}
__device__ __forceinline__ void ldsm_x4(uint32_t& r0, uint32_t& r1, uint32_t& r2,
                                        uint32_t& r3, uint32_t addr) {
    asm volatile("ldmatrix.sync.aligned.m8n8.x4.shared.b16 {%0,%1,%2,%3}, [%4];"
                 : "=r"(r0), "=r"(r1), "=r"(r2), "=r"(r3) : "r"(addr));
}

template<int NW, bool PERB, bool BIAS>
__global__ __launch_bounds__(256)
void gemm_h_k(const __half* __restrict__ A, const __half* __restrict__ WtB,
              const float* __restrict__ bias, const float* __restrict__ illu,
              void* __restrict__ C0, void* __restrict__ C1, void* __restrict__ C2)
{
    extern __shared__ __align__(16) __half smem[];
    int tid = threadIdx.x;
    int wid = tid >> 5, lane = tid & 31;
    int g = lane >> 2, t = lane & 3;
    int wm = wid & 1, wn = wid >> 1;

    int widx  = blockIdx.x >> 2;
    int ntile = blockIdx.x & 3;
    int n0 = ntile * 128;
    int m0 = blockIdx.y * 128;
    int batch = m0 >> 14;

    const __half* Wp = WtB + (size_t)widx*262144 + (PERB ? (size_t)batch*262144 : 0)
                     + (size_t)n0*512;
    bool outhalf = (NW == 3 && widx < 2);
    void* Cout = (NW == 1) ? C0 : ((widx == 0) ? C0 : (widx == 1) ? C1 : C2);

    uint32_t smbase = (uint32_t)__cvta_generic_to_shared(smem);
    uint32_t laneA = (uint32_t)(((lane & 15)*KPADH + ((lane >> 4) << 3)) * 2);
    uint32_t laneB = (uint32_t)(((((lane >> 4) << 3) + (lane & 7))*KPADH + (lane & 8)) * 2);

    float acc[4][4][4];
    #pragma unroll
    for (int i = 0; i < 4; ++i)
        #pragma unroll
        for (int j = 0; j < 4; ++j)
            #pragma unroll
            for (int q = 0; q < 4; ++q) acc[i][j][q] = 0.f;

    auto cpStage = [&](int kt, int stage) {
        __half* As = smem + stage*2*HBUF;
        __half* Bs = As + HBUF;
        #pragma unroll
        for (int j = 0; j < 2; ++j) {
            int f = j*256 + tid;
            int row = f >> 2, c8 = f & 3;
            const __half* srcA = A + (size_t)(m0 + row)*512 + kt*32 + c8*8;
            asm volatile("cp.async.cg.shared.global [%0], [%1], 16;"
                :: "l"((uint64_t)__cvta_generic_to_shared(As + row*KPADH + c8*8)),
                   "l"(srcA) : "memory");
            const __half* srcB = Wp + (size_t)row*512 + kt*32 + c8*8;
            asm volatile("cp.async.cg.shared.global [%0], [%1], 16;"
                :: "l"((uint64_t)__cvta_generic_to_shared(Bs + row*KPADH + c8*8)),
                   "l"(srcB) : "memory");
        }
        asm volatile("cp.async.commit_group;" ::: "memory");
    };

    cpStage(0, 0);
    cpStage(1, 1);

    #pragma unroll 1
    for (int kt = 0; kt < 16; ++kt) {
        int stage = kt - (kt/3)*3;
        if (kt == 15) asm volatile("cp.async.wait_group 0;" ::: "memory");
        else          asm volatile("cp.async.wait_group 1;" ::: "memory");
        __syncthreads();
        if (kt + 2 < 16) {
            int s2 = (kt+2) - ((kt+2)/3)*3;
            cpStage(kt + 2, s2);
        }
        uint32_t stbase = smbase + (uint32_t)(stage*2*HBUF*2);
        uint32_t ab = stbase + (uint32_t)(wm*64*KPADH*2) + laneA;
        uint32_t bb = stbase + (uint32_t)(HBUF*2) + (uint32_t)(wn*32*KPADH*2) + laneB;
        #pragma unroll
        for (int kk = 0; kk < 2; ++kk) {
            uint32_t af[4][4], bf[4][2];
            #pragma unroll
            for (int mt = 0; mt < 4; ++mt)
                ldsm_x4(af[mt][0], af[mt][1], af[mt][2], af[mt][3],
                        ab + (uint32_t)(mt*16*KPADH*2 + kk*32));
            #pragma unroll
            for (int np = 0; np < 2; ++np)
                ldsm_x4(bf[np*2][0], bf[np*2][1], bf[np*2+1][0], bf[np*2+1][1],
                        bb + (uint32_t)(np*16*KPADH*2 + kk*32));
            #pragma unroll
            for (int mt = 0; mt < 4; ++mt)
                #pragma unroll
                for (int nt = 0; nt < 4; ++nt)
                    mma_f16(acc[mt][nt][0], acc[mt][nt][1],
                            acc[mt][nt][2], acc[mt][nt][3],
                            af[mt][0], af[mt][1], af[mt][2], af[mt][3],
                            bf[nt][0], bf[nt][1]);
        }
    }

    // ---- epilogue ----
    #pragma unroll
    for (int mt = 0; mt < 4; ++mt) {
        int r0 = m0 + wm*64 + mt*16 + g;
        #pragma unroll
        for (int nt = 0; nt < 4; ++nt) {
            int col = n0 + wn*32 + nt*8 + 2*t;
            if (outhalf) {
                __half2 h0 = __floats2half2_rn(acc[mt][nt][0], acc[mt][nt][1]);
                __half2 h1 = __floats2half2_rn(acc[mt][nt][2], acc[mt][nt][3]);
                *(__half2*)((__half*)Cout + (size_t)r0*512 + col)     = h0;
                *(__half2*)((__half*)Cout + (size_t)(r0+8)*512 + col) = h1;
            } else {
                float bx = 0.f, by = 0.f;
                if (BIAS) { bx = bias[col]; by = bias[col + 1]; }
                float2 v0 = { acc[mt][nt][0] + bx, acc[mt][nt][1] + by };
                float2 v1 = { acc[mt][nt][2] + bx, acc[mt][nt][3] + by };
                *(float2*)((float*)Cout + (size_t)r0*512 + col)     = v0;
                *(float2*)((float*)Cout + (size_t)(r0+8)*512 + col) = v1;
                if (NW == 3) {
                    float2 i0 = *(const float2*)(illu + (size_t)r0*512 + col);
                    float2 i1 = *(const float2*)(illu + (size_t)(r0+8)*512 + col);
                    __half2 h0 = __floats2half2_rn(v0.x*i0.x, v0.y*i0.y);
                    __half2 h1 = __floats2half2_rn(v1.x*i1.x, v1.y*i1.y);
                    *(__half2*)(g_vh + (size_t)r0*512 + col)     = h0;
                    *(__half2*)(g_vh + (size_t)(r0+8)*512 + col) = h1;
                }
            }
        }
    }
}

// ---------------- Gram + column norms (32-row chunks) ------------------------
__global__ __launch_bounds__(256) void gram_k() {
    int bh = blockIdx.x >> 3;
    int chunk = blockIdx.x & 7;
    int b = bh >> 3, h = bh & 7;
    int tid = threadIdx.x;
    __shared__ float qs[32][64], ks[32][64];
    float acc[4][4] = {{0.f}};
    float sq = 0.f, sk = 0.f;
    int ti = tid >> 4, tj = tid & 15;
    const __half* qbase = g_q + (size_t)b*NN*512 + h*64;
    const __half* kbase = g_k + (size_t)b*NN*512 + h*64;
    int n0 = chunk * 2048;
    for (int n = n0; n < n0 + 2048; n += 32) {
        __syncthreads();
        #pragma unroll
        for (int j = 0; j < 4; ++j) {
            int l = j*256 + tid;
            int nn = l >> 5, h2 = l & 31;
            size_t off = (size_t)(n + nn)*512 + h2*2;
            float2 fq = __half22float2(*(const __half2*)(qbase + off));
            float2 fk = __half22float2(*(const __half2*)(kbase + off));
            qs[nn][h2*2] = fq.x; qs[nn][h2*2+1] = fq.y;
            ks[nn][h2*2] = fk.x; ks[nn][h2*2+1] = fk.y;
        }
        __syncthreads();
        #pragma unroll 4
        for (int nn = 0; nn < 32; ++nn) {
            float kv[4], qv[4];
            #pragma unroll
            for (int ii = 0; ii < 4; ++ii) kv[ii] = ks[nn][ti*4+ii];
            #pragma unroll
            for (int jj = 0; jj < 4; ++jj) qv[jj] = qs[nn][tj*4+jj];
            #pragma unroll
            for (int ii = 0; ii < 4; ++ii)
                #pragma unroll
                for (int jj = 0; jj < 4; ++jj)
                    acc[ii][jj] = fmaf(kv[ii], qv[jj], acc[ii][jj]);
        }
        if (tid < 64) {
            #pragma unroll 8
            for (int nn = 0; nn < 32; ++nn) sq = fmaf(qs[nn][tid], qs[nn][tid], sq);
        } else if (tid < 128) {
            #pragma unroll 8
            for (int nn = 0; nn < 32; ++nn) sk = fmaf(ks[nn][tid-64], ks[nn][tid-64], sk);
        }
    }
    float* gp = g_gram + (size_t)bh*4096;
    #pragma unroll
    for (int ii = 0; ii < 4; ++ii)
        #pragma unroll
        for (int jj = 0; jj < 4; ++jj)
            atomicAdd(&gp[(ti*4+ii)*64 + tj*4+jj], acc[ii][jj]);
    if (tid < 64) atomicAdd(&g_ssq[bh*64 + tid], sq);
    else if (tid < 128) atomicAdd(&g_ssk[bh*64 + tid - 64], sk);
}

// ---------------- softmax ----------------------------------------------------
__global__ void softmax_k(const float* __restrict__ rescale) {
    int bh = blockIdx.x;
    int h = bh & 7;
    int i = threadIdx.x;
    __shared__ float rq[64];
    rq[i] = 1.f / fmaxf(sqrtf(g_ssq[bh*64 + i]), 1e-12f);
    __syncthreads();
    float rk = 1.f / fmaxf(sqrtf(g_ssk[bh*64 + i]), 1e-12f);
    float rs = rescale[h];
    const float* gp = g_gram + (size_t)bh*4096 + i*64;
    float vals[64];
    float mx = -1e30f;
    #pragma unroll
    for (int j = 0; j < 64; ++j) {
        vals[j] = gp[j] * rk * rq[j] * rs;
        mx = fmaxf(mx, vals[j]);
    }
    float s = 0.f;
    #pragma unroll
    for (int j = 0; j < 64; ++j) { vals[j] = expf(vals[j] - mx); s += vals[j]; }
    float inv = 1.f / s;
    float* ap = g_attn + (size_t)bh*4096 + i*64;
    #pragma unroll
    for (int j = 0; j < 64; ++j) ap[j] = vals[j] * inv;
}

// ------- fold attn into wproj, TRANSPOSED half output ------------------------
__global__ __launch_bounds__(512) void fold_kT(const float* __restrict__ wproj) {
    int b = blockIdx.x >> 3, h = blockIdx.x & 7;
    int o = threadIdx.x;
    __shared__ float sa[64*64];
    const float* ap = g_attn + (size_t)(b*8 + h)*4096;
    for (int l = o; l < 4096; l += 512) sa[l] = ap[l];
    __syncthreads();
    float wp[64];
    #pragma unroll
    for (int i = 0; i < 64; ++i) wp[i] = wproj[(h*64 + i)*512 + o];
    __half* dst = g_wfoldt + (size_t)b*262144 + (size_t)o*512 + h*64;
    #pragma unroll 4
    for (int j = 0; j < 64; ++j) {
        float acc = 0.f;
        #pragma unroll
        for (int i = 0; i < 64; ++i) acc = fmaf(sa[i*64 + j], wp[i], acc);
        dst[j] = __float2half_rn(acc);
    }
}

// ---------------- fused double 3x3 depthwise conv + gelu ---------------------
#define DW_SMEM ((144+100)*64*4)
__global__ __launch_bounds__(256) void dwconv_fused_k(const float* __restrict__ vi,
                                                      const float* __restrict__ w1g,
                                                      const float* __restrict__ w2g,
                                                      float* __restrict__ out) {
    extern __shared__ float sm[];
    float* vt = sm;
    float* pt = sm + 144*64;
    int bz = blockIdx.z;
    int b = bz >> 3;
    int c0 = (bz & 7) * 64;
    int y0 = blockIdx.y * 8, x0 = blockIdx.x * 8;
    int tid = threadIdx.x;
    int c = tid & 63;
    int pg = tid >> 6;
    for (int p = pg; p < 144; p += 4) {
        int gy = y0 - 2 + p/12, gx = x0 - 2 + p%12;
        float v = 0.f;
        if (gy >= 0 && gy < HH && gx >= 0 && gx < WWW)
            v = vi[((size_t)(b*HH + gy)*WWW + gx)*CC + c0 + c];
        vt[p*64 + c] = v;
    }
    float w1[9], w2[9];
    #pragma unroll
    for (int t = 0; t < 9; ++t) {
        w1[t] = w1g[(c0 + c)*9 + t];
        w2[t] = w2g[(c0 + c)*9 + t];
    }
    __syncthreads();
    for (int p = pg; p < 100; p += 4) {
        int py = p/10, px = p%10;
        int gy = y0 - 1 + py, gx = x0 - 1 + px;
        float acc = 0.f;
        #pragma unroll
        for (int dy = 0; dy < 3; ++dy)
            #pragma unroll
            for (int dx = 0; dx < 3; ++dx)
                acc = fmaf(vt[((py+dy)*12 + px+dx)*64 + c], w1[dy*3+dx], acc);
        acc = 0.5f*acc*(1.f + erff(acc*0.70710678118654752f));
        if (gy < 0 || gy >= HH || gx < 0 || gx >= WWW) acc = 0.f;
        pt[p*64 + c] = acc;
    }
    __syncthreads();
    for (int p = pg; p < 64; p += 4) {
        int oy = p >> 3, ox = p & 7;
        float acc = 0.f;
        #pragma unroll
        for (int dy = 0; dy < 3; ++dy)
            #pragma unroll
            for (int dx = 0; dx < 3; ++dx)
                acc = fmaf(pt[((oy+dy)*10 + ox+dx)*64 + c], w2[dy*3+dx], acc);
        out[((size_t)(b*HH + y0+oy)*WWW + x0+ox)*CC + c0 + c] += acc;
    }
}

// ---------------------------------------------------------------------------
extern "C" void kernel_launch(void* const* d_in, const int* in_sizes, int n_in,
                              void* d_out, int out_size) {
    const float* x_in    = (const float*)d_in[0];
    const float* illu    = (const float*)d_in[1];
    const float* prior   = (const float*)d_in[2];
    const float* wq      = (const float*)d_in[3];
    const float* wk      = (const float*)d_in[4];
    const float* wv      = (const float*)d_in[5];
    const float* rescale = (const float*)d_in[6];
    const float* wproj   = (const float*)d_in[7];
    const float* bproj   = (const float*)d_in[8];
    const float* cw1     = (const float*)d_in[9];
    const float* cw2     = (const float*)d_in[10];
    const float* pw1     = (const float*)d_in[11];
    const float* pw2     = (const float*)d_in[12];
    float* out = (float*)d_out;

    float *p_vi, *p_tmp, *p_cdp;
    __half *p_xh, *p_vh, *p_q, *p_k, *p_wt, *p_wfoldt;
    cudaGetSymbolAddress((void**)&p_xh,     g_xh);
    cudaGetSymbolAddress((void**)&p_vh,     g_vh);
    cudaGetSymbolAddress((void**)&p_q,      g_q);
    cudaGetSymbolAddress((void**)&p_k,      g_k);
    cudaGetSymbolAddress((void**)&p_vi,     g_vi);
    cudaGetSymbolAddress((void**)&p_tmp,    g_tmp);
    cudaGetSymbolAddress((void**)&p_cdp,    g_cdp);
    cudaGetSymbolAddress((void**)&p_wt,     g_wt);
    cudaGetSymbolAddress((void**)&p_wfoldt, g_wfoldt);

    cudaFuncSetAttribute(gemm_h_k<3,false,false>,
                         cudaFuncAttributeMaxDynamicSharedMemorySize, GEMM_SMEM);
    cudaFuncSetAttribute(gemm_h_k<1,true,true>,
                         cudaFuncAttributeMaxDynamicSharedMemorySize, GEMM_SMEM);
    cudaFuncSetAttribute(dwconv_fused_k,
                         cudaFuncAttributeMaxDynamicSharedMemorySize, DW_SMEM);

    zero_small_k<<<512, 256>>>();
    small_gemm_k<<<(NBATCH*2048 + 255)/256, 256>>>(prior, cw1, p_tmp, 512, 2048);
    small_gemm_k<<<(NBATCH*1024 + 255)/256, 256>>>(p_tmp, cw2, p_cdp, 2048, 1024);
    dim3 tb(32, 8), tg(16, 16, 3);
    transp3_k<<<tg, tb>>>(wq, wk, wv, p_wt);
    modulate_k<<<(MTOT*CC/4 + 255)/256, 256>>>(x_in);

    dim3 gq(12, 512);
    gemm_h_k<3,false,false><<<gq, 256, GEMM_SMEM>>>(
        p_xh, p_wt, nullptr, illu, p_q, p_k, p_vi);

    gram_k<<<256, 256>>>();
    softmax_k<<<32, 64>>>(rescale);
    fold_kT<<<32, 512>>>(wproj);

    dim3 gf(4, 512);
    gemm_h_k<1,true,true><<<gf, 256, GEMM_SMEM>>>(
        p_vh, p_wfoldt, bproj, nullptr, out, out, out);

    dim3 cg(WWW/8, HH/8, NBATCH*8);
    dwconv_fused_k<<<cg, 256, DW_SMEM>>>(p_vi, pw1, pw2, out);
}

// round 17
// speedup vs baseline: 1.3585x; 1.2363x over previous
#include <cuda_runtime.h>
#include <cuda_fp16.h>
#include <math.h>
#include <stdint.h>

#define NBATCH 4
#define HH 128
#define WWW 128
#define CC 512
#define NN 16384
#define NHEADS 8
#define DHEAD 64
#define MTOT (NBATCH*NN)

// ---------------- scratch ---------------------------------------------------
__device__ __half g_xh[MTOT*CC];
__device__ __half g_vh[MTOT*CC];          // v_inp*illu
__device__ __half g_vih[MTOT*CC];         // v_inp (for PE branch)
__device__ __half g_q [MTOT*CC];
__device__ __half g_k [MTOT*CC];
__device__ float  g_tmp[NBATCH*2048];
__device__ float  g_cdp[NBATCH*1024];
__device__ float  g_gram[NBATCH*NHEADS*64*64];
__device__ float  g_ssq[NBATCH*NHEADS*64];
__device__ float  g_ssk[NBATCH*NHEADS*64];
__device__ float  g_attn[NBATCH*NHEADS*64*64];
__device__ __half g_wt[3*CC*CC];
__device__ __half g_wfoldt[NBATCH*CC*CC];

// ---------------- helpers ----------------------------------------------------
__device__ __forceinline__ void mma_f16(
    float& d0, float& d1, float& d2, float& d3,
    uint32_t a0, uint32_t a1, uint32_t a2, uint32_t a3, uint32_t b0, uint32_t b1)
{
    asm volatile(
        "mma.sync.aligned.m16n8k16.row.col.f32.f16.f16.f32 "
        "{%0,%1,%2,%3}, {%4,%5,%6,%7}, {%8,%9}, {%0,%1,%2,%3};"
        : "+f"(d0), "+f"(d1), "+f"(d2), "+f"(d3)
        : "r"(a0), "r"(a1), "r"(a2), "r"(a3), "r"(b0), "r"(b1));
}
__device__ __forceinline__ void ldsm_x4(uint32_t& r0, uint32_t& r1, uint32_t& r2,
                                        uint32_t& r3, uint32_t addr) {
    asm volatile("ldmatrix.sync.aligned.m8n8.x4.shared.b16 {%0,%1,%2,%3}, [%4];"
                 : "=r"(r0), "=r"(r1), "=r"(r2), "=r"(r3) : "r"(addr));
}
__device__ __forceinline__ void ldsm_x4t(uint32_t& r0, uint32_t& r1, uint32_t& r2,
                                         uint32_t& r3, uint32_t addr) {
    asm volatile("ldmatrix.sync.aligned.m8n8.x4.trans.shared.b16 {%0,%1,%2,%3}, [%4];"
                 : "=r"(r0), "=r"(r1), "=r"(r2), "=r"(r3) : "r"(addr));
}
__device__ __forceinline__ void cpasync16(void* dst, const void* src) {
    asm volatile("cp.async.cg.shared.global [%0], [%1], 16;"
        :: "l"((uint64_t)__cvta_generic_to_shared(dst)), "l"(src) : "memory");
}

// ---------------- zero accumulators -----------------------------------------
__global__ void zero_small_k() {
    int i = blockIdx.x*blockDim.x + threadIdx.x;
    if (i < NBATCH*NHEADS*64*64) g_gram[i] = 0.f;
    if (i < NBATCH*NHEADS*64) { g_ssq[i] = 0.f; g_ssk[i] = 0.f; }
}

// ---------------- tiny dense (cdp chain) ------------------------------------
__global__ void small_gemm_k(const float* __restrict__ A, const float* __restrict__ Wm,
                             float* __restrict__ out, int K, int Nc) {
    int idx = blockIdx.x*blockDim.x + threadIdx.x;
    if (idx >= NBATCH*Nc) return;
    int b = idx / Nc, j = idx - b*Nc;
    const float* a = A + b*K;
    float acc = 0.f;
    for (int k = 0; k < K; ++k) acc = fmaf(a[k], Wm[k*Nc + j], acc);
    out[idx] = acc;
}

// ---------------- 3x transpose 512x512 -> half -------------------------------
__global__ void transp3_k(const float* __restrict__ w0, const float* __restrict__ w1,
                          const float* __restrict__ w2, __half* __restrict__ Wt) {
    const float* W = (blockIdx.z == 0) ? w0 : (blockIdx.z == 1) ? w1 : w2;
    __half* dst = Wt + (size_t)blockIdx.z * 262144;
    __shared__ float t[32][33];
    int x0 = blockIdx.x*32, y0 = blockIdx.y*32;
    int tx = threadIdx.x, ty = threadIdx.y;
    #pragma unroll
    for (int i = 0; i < 4; ++i)
        t[ty + i*8][tx] = W[(size_t)(y0 + ty + i*8)*512 + x0 + tx];
    __syncthreads();
    #pragma unroll
    for (int i = 0; i < 4; ++i)
        dst[(size_t)(x0 + ty + i*8)*512 + y0 + tx] = __float2half_rn(t[tx][ty + i*8]);
}

// ---------------- xm = x*cdp1+cdp2 -> half -----------------------------------
__global__ void modulate_k(const float* __restrict__ x) {
    long long i = (long long)blockIdx.x*blockDim.x + threadIdx.x;
    long long e = i*4;
    int c = (int)(e & (CC-1));
    int b = (int)(e >> 23);
    float4 xv = ((const float4*)x)[i];
    float4 s = *(const float4*)&g_cdp[b*1024 + c];
    float4 t = *(const float4*)&g_cdp[b*1024 + 512 + c];
    __half2 h0 = __floats2half2_rn(fmaf(xv.x, s.x, t.x), fmaf(xv.y, s.y, t.y));
    __half2 h1 = __floats2half2_rn(fmaf(xv.z, s.z, t.z), fmaf(xv.w, s.w, t.w));
    ((__half2*)g_xh)[i*2]   = h0;
    ((__half2*)g_xh)[i*2+1] = h1;
}

// ---------------- fp16 mma.sync GEMM, 2-stage x 64-K chunks ------------------
#define KP2 72
#define STG (128*KP2)                      // halfs per operand per stage
#define GEMM_SMEM (4*STG*2)                // 73728 bytes

template<int NW, bool PERB, bool BIAS>
__global__ __launch_bounds__(256)
void gemm_h_k(const __half* __restrict__ A, const __half* __restrict__ WtB,
              const float* __restrict__ bias, const float* __restrict__ illu,
              void* __restrict__ C0, void* __restrict__ C1)
{
    extern __shared__ __align__(16) __half smem[];
    int tid = threadIdx.x;
    int wid = tid >> 5, lane = tid & 31;
    int g = lane >> 2, t = lane & 3;
    int wm = wid & 1, wn = wid >> 1;

    int widx  = blockIdx.x >> 2;
    int ntile = blockIdx.x & 3;
    int n0 = ntile * 128;
    int m0 = blockIdx.y * 128;
    int batch = m0 >> 14;

    const __half* Wp = WtB + (size_t)widx*262144 + (PERB ? (size_t)batch*262144 : 0)
                     + (size_t)n0*512;

    uint32_t smbase = (uint32_t)__cvta_generic_to_shared(smem);
    uint32_t laneA = (uint32_t)(((lane & 15)*KP2 + ((lane >> 4) << 3)) * 2);
    uint32_t laneB = (uint32_t)(((((lane >> 4) << 3) + (lane & 7))*KP2 + (lane & 8)) * 2);

    float acc[4][4][4];
    #pragma unroll
    for (int i = 0; i < 4; ++i)
        #pragma unroll
        for (int j = 0; j < 4; ++j)
            #pragma unroll
            for (int q = 0; q < 4; ++q) acc[i][j][q] = 0.f;

    auto cpStage = [&](int kt, int s) {
        __half* As = smem + s*2*STG;
        __half* Bs = As + STG;
        #pragma unroll
        for (int u = 0; u < 4; ++u) {            // A: 128 rows x 8 segs = 1024
            int f = u*256 + tid;
            int row = f >> 3, seg = f & 7;
            cpasync16(As + row*KP2 + seg*8,
                      A + (size_t)(m0 + row)*512 + kt*64 + seg*8);
        }
        #pragma unroll
        for (int u = 0; u < 4; ++u) {            // B
            int f = u*256 + tid;
            int row = f >> 3, seg = f & 7;
            cpasync16(Bs + row*KP2 + seg*8,
                      Wp + (size_t)row*512 + kt*64 + seg*8);
        }
        asm volatile("cp.async.commit_group;" ::: "memory");
    };

    cpStage(0, 0);

    #pragma unroll 1
    for (int c = 0; c < 8; ++c) {
        if (c < 7) {
            cpStage(c + 1, (c + 1) & 1);
            asm volatile("cp.async.wait_group 1;" ::: "memory");
        } else {
            asm volatile("cp.async.wait_group 0;" ::: "memory");
        }
        __syncthreads();
        uint32_t stbase = smbase + (uint32_t)((c & 1)*2*STG*2);
        uint32_t ab = stbase + (uint32_t)(wm*64*KP2*2) + laneA;
        uint32_t bb = stbase + (uint32_t)(STG*2) + (uint32_t)(wn*32*KP2*2) + laneB;
        #pragma unroll
        for (int kk = 0; kk < 4; ++kk) {
            uint32_t af[4][4], bf[4][2];
            #pragma unroll
            for (int mt = 0; mt < 4; ++mt)
                ldsm_x4(af[mt][0], af[mt][1], af[mt][2], af[mt][3],
                        ab + (uint32_t)(mt*16*KP2*2 + kk*32));
            #pragma unroll
            for (int np = 0; np < 2; ++np)
                ldsm_x4(bf[np*2][0], bf[np*2][1], bf[np*2+1][0], bf[np*2+1][1],
                        bb + (uint32_t)(np*16*KP2*2 + kk*32));
            #pragma unroll
            for (int mt = 0; mt < 4; ++mt)
                #pragma unroll
                for (int nt = 0; nt < 4; ++nt)
                    mma_f16(acc[mt][nt][0], acc[mt][nt][1],
                            acc[mt][nt][2], acc[mt][nt][3],
                            af[mt][0], af[mt][1], af[mt][2], af[mt][3],
                            bf[nt][0], bf[nt][1]);
        }
        __syncthreads();
    }

    // ---- epilogue ----
    #pragma unroll
    for (int mt = 0; mt < 4; ++mt) {
        int r0 = m0 + wm*64 + mt*16 + g;
        #pragma unroll
        for (int nt = 0; nt < 4; ++nt) {
            int col = n0 + wn*32 + nt*8 + 2*t;
            if (NW == 3 && widx == 2) {
                // v: vih (half) + vh = v*illu (half)
                __half2 h0 = __floats2half2_rn(acc[mt][nt][0], acc[mt][nt][1]);
                __half2 h1 = __floats2half2_rn(acc[mt][nt][2], acc[mt][nt][3]);
                *(__half2*)(g_vih + (size_t)r0*512 + col)     = h0;
                *(__half2*)(g_vih + (size_t)(r0+8)*512 + col) = h1;
                float2 i0 = *(const float2*)(illu + (size_t)r0*512 + col);
                float2 i1 = *(const float2*)(illu + (size_t)(r0+8)*512 + col);
                __half2 v0 = __floats2half2_rn(acc[mt][nt][0]*i0.x, acc[mt][nt][1]*i0.y);
                __half2 v1 = __floats2half2_rn(acc[mt][nt][2]*i1.x, acc[mt][nt][3]*i1.y);
                *(__half2*)(g_vh + (size_t)r0*512 + col)     = v0;
                *(__half2*)(g_vh + (size_t)(r0+8)*512 + col) = v1;
            } else if (NW == 3) {
                __half* Cout = (widx == 0) ? (__half*)C0 : (__half*)C1;
                __half2 h0 = __floats2half2_rn(acc[mt][nt][0], acc[mt][nt][1]);
                __half2 h1 = __floats2half2_rn(acc[mt][nt][2], acc[mt][nt][3]);
                *(__half2*)(Cout + (size_t)r0*512 + col)     = h0;
                *(__half2*)(Cout + (size_t)(r0+8)*512 + col) = h1;
            } else {
                float bx = bias[col], by = bias[col + 1];
                float2 v0 = { acc[mt][nt][0] + bx, acc[mt][nt][1] + by };
                float2 v1 = { acc[mt][nt][2] + bx, acc[mt][nt][3] + by };
                *(float2*)((float*)C0 + (size_t)r0*512 + col)     = v0;
                *(float2*)((float*)C0 + (size_t)(r0+8)*512 + col) = v1;
            }
        }
    }
}

// ---------------- Gram via mma: G = K^T Q, plus column norms -----------------
#define GR_PAD 72
__global__ __launch_bounds__(256) void gram_mma_k() {
    __shared__ __align__(16) __half qs[2][64*GR_PAD];
    __shared__ __align__(16) __half ks[2][64*GR_PAD];
    int bh = blockIdx.x >> 3;
    int chunk0 = (blockIdx.x & 7) * 2048;
    int b = bh >> 3, h = bh & 7;
    int tid = threadIdx.x, wid = tid >> 5, lane = tid & 31;
    int g = lane >> 2, t = lane & 3;
    int wi = wid & 3, wj = wid >> 2;          // i-tile 16, j-tile 32
    const __half* qbase = g_q + (size_t)b*NN*512 + h*64;
    const __half* kbase = g_k + (size_t)b*NN*512 + h*64;

    float acc[4][4];
    #pragma unroll
    for (int i = 0; i < 4; ++i)
        #pragma unroll
        for (int j = 0; j < 4; ++j) acc[i][j] = 0.f;
    float sq = 0.f, sk = 0.f;
    int sch = tid & 63, srow0 = tid >> 6;

    uint32_t aOffA = (uint32_t)(((((lane>>4)&1)*8 + (lane&7))*GR_PAD + (lane&8)) * 2);
    uint32_t aOffB = (uint32_t)(((((lane>>3)&1)*8 + (lane&7))*GR_PAD + ((lane>>4)&1)*8) * 2);
    uint32_t ksb = (uint32_t)__cvta_generic_to_shared(&ks[0][0]);
    uint32_t qsb = (uint32_t)__cvta_generic_to_shared(&qs[0][0]);

    auto cpStage = [&](int c, int s) {
        int nr0 = chunk0 + c*64;
        #pragma unroll
        for (int u = 0; u < 2; ++u) {
            int f = u*256 + tid;
            int row = f >> 3, seg = f & 7;
            cpasync16(&qs[s][row*GR_PAD + seg*8],
                      qbase + (size_t)(nr0 + row)*512 + seg*8);
            cpasync16(&ks[s][row*GR_PAD + seg*8],
                      kbase + (size_t)(nr0 + row)*512 + seg*8);
        }
        asm volatile("cp.async.commit_group;" ::: "memory");
    };

    cpStage(0, 0);
    #pragma unroll 1
    for (int c = 0; c < 32; ++c) {
        if (c < 31) {
            cpStage(c + 1, (c + 1) & 1);
            asm volatile("cp.async.wait_group 1;" ::: "memory");
        } else {
            asm volatile("cp.async.wait_group 0;" ::: "memory");
        }
        __syncthreads();
        int s = c & 1;
        uint32_t kst = ksb + (uint32_t)(s*64*GR_PAD*2);
        uint32_t qst = qsb + (uint32_t)(s*64*GR_PAD*2);
        #pragma unroll
        for (int ksi = 0; ksi < 4; ++ksi) {
            uint32_t a0,a1,a2,a3;
            ldsm_x4t(a0,a1,a2,a3, kst + aOffA + (uint32_t)(ksi*16*GR_PAD*2 + wi*16*2));
            uint32_t b0[4],b1[4];
            #pragma unroll
            for (int p = 0; p < 2; ++p) {
                uint32_t r0,r1,r2,r3;
                ldsm_x4t(r0,r1,r2,r3, qst + aOffB +
                         (uint32_t)(ksi*16*GR_PAD*2 + (wj*32 + p*16)*2));
                b0[p*2] = r0; b1[p*2] = r1; b0[p*2+1] = r2; b1[p*2+1] = r3;
            }
            #pragma unroll
            for (int jt = 0; jt < 4; ++jt)
                mma_f16(acc[jt][0], acc[jt][1], acc[jt][2], acc[jt][3],
                        a0, a1, a2, a3, b0[jt], b1[jt]);
        }
        #pragma unroll 4
        for (int r = 0; r < 16; ++r) {
            int row = srow0 + r*4;
            float qv = __half2float(qs[s][row*GR_PAD + sch]);
            float kv = __half2float(ks[s][row*GR_PAD + sch]);
            sq = fmaf(qv, qv, sq);
            sk = fmaf(kv, kv, sk);
        }
        __syncthreads();
    }

    float* gp = g_gram + (size_t)bh*4096;
    #pragma unroll
    for (int jt = 0; jt < 4; ++jt) {
        int j = wj*32 + jt*8 + 2*t;
        int i0 = wi*16 + g;
        atomicAdd(&gp[i0*64 + j],       acc[jt][0]);
        atomicAdd(&gp[i0*64 + j + 1],   acc[jt][1]);
        atomicAdd(&gp[(i0+8)*64 + j],   acc[jt][2]);
        atomicAdd(&gp[(i0+8)*64 + j+1], acc[jt][3]);
    }
    atomicAdd(&g_ssq[bh*64 + sch], sq);
    atomicAdd(&g_ssk[bh*64 + sch], sk);
}

// ---------------- softmax ----------------------------------------------------
__global__ void softmax_k(const float* __restrict__ rescale) {
    int bh = blockIdx.x;
    int h = bh & 7;
    int i = threadIdx.x;
    __shared__ float rq[64];
    rq[i] = 1.f / fmaxf(sqrtf(g_ssq[bh*64 + i]), 1e-12f);
    __syncthreads();
    float rk = 1.f / fmaxf(sqrtf(g_ssk[bh*64 + i]), 1e-12f);
    float rs = rescale[h];
    const float* gp = g_gram + (size_t)bh*4096 + i*64;
    float vals[64];
    float mx = -1e30f;
    #pragma unroll
    for (int j = 0; j < 64; ++j) {
        vals[j] = gp[j] * rk * rq[j] * rs;
        mx = fmaxf(mx, vals[j]);
    }
    float s = 0.f;
    #pragma unroll
    for (int j = 0; j < 64; ++j) { vals[j] = expf(vals[j] - mx); s += vals[j]; }
    float inv = 1.f / s;
    float* ap = g_attn + (size_t)bh*4096 + i*64;
    #pragma unroll
    for (int j = 0; j < 64; ++j) ap[j] = vals[j] * inv;
}

// ------- fold attn into wproj, TRANSPOSED half output ------------------------
__global__ __launch_bounds__(512) void fold_kT(const float* __restrict__ wproj) {
    int b = blockIdx.x >> 3, h = blockIdx.x & 7;
    int o = threadIdx.x;
    __shared__ float sa[64*64];
    const float* ap = g_attn + (size_t)(b*8 + h)*4096;
    for (int l = o; l < 4096; l += 512) sa[l] = ap[l];
    __syncthreads();
    float wp[64];
    #pragma unroll
    for (int i = 0; i < 64; ++i) wp[i] = wproj[(h*64 + i)*512 + o];
    __half* dst = g_wfoldt + (size_t)b*262144 + (size_t)o*512 + h*64;
    #pragma unroll 4
    for (int j = 0; j < 64; ++j) {
        float acc = 0.f;
        #pragma unroll
        for (int i = 0; i < 64; ++i) acc = fmaf(sa[i*64 + j], wp[i], acc);
        dst[j] = __float2half_rn(acc);
    }
}

// ---------------- fused double 3x3 depthwise conv + gelu (half in) -----------
#define DW_SMEM ((144+100)*64*4)
__global__ __launch_bounds__(256) void dwconv_fused_k(const __half* __restrict__ vih,
                                                      const float* __restrict__ w1g,
                                                      const float* __restrict__ w2g,
                                                      float* __restrict__ out) {
    extern __shared__ float sm[];
    float* vt = sm;
    float* pt = sm + 144*64;
    int bz = blockIdx.z;
    int b = bz >> 3;
    int c0 = (bz & 7) * 64;
    int y0 = blockIdx.y * 8, x0 = blockIdx.x * 8;
    int tid = threadIdx.x;
    int c = tid & 63;
    int pg = tid >> 6;
    for (int p = pg; p < 144; p += 4) {
        int gy = y0 - 2 + p/12, gx = x0 - 2 + p%12;
        float v = 0.f;
        if (gy >= 0 && gy < HH && gx >= 0 && gx < WWW)
            v = __half2float(vih[((size_t)(b*HH + gy)*WWW + gx)*CC + c0 + c]);
        vt[p*64 + c] = v;
    }
    float w1[9], w2[9];
    #pragma unroll
    for (int t = 0; t < 9; ++t) {
        w1[t] = w1g[(c0 + c)*9 + t];
        w2[t] = w2g[(c0 + c)*9 + t];
    }
    __syncthreads();
    for (int p = pg; p < 100; p += 4) {
        int py = p/10, px = p%10;
        int gy = y0 - 1 + py, gx = x0 - 1 + px;
        float acc = 0.f;
        #pragma unroll
        for (int dy = 0; dy < 3; ++dy)
            #pragma unroll
            for (int dx = 0; dx < 3; ++dx)
                acc = fmaf(vt[((py+dy)*12 + px+dx)*64 + c], w1[dy*3+dx], acc);
        acc = 0.5f*acc*(1.f + erff(acc*0.70710678118654752f));
        if (gy < 0 || gy >= HH || gx < 0 || gx >= WWW) acc = 0.f;
        pt[p*64 + c] = acc;
    }
    __syncthreads();
    for (int p = pg; p < 64; p += 4) {
        int oy = p >> 3, ox = p & 7;
        float acc = 0.f;
        #pragma unroll
        for (int dy = 0; dy < 3; ++dy)
            #pragma unroll
            for (int dx = 0; dx < 3; ++dx)
                acc = fmaf(pt[((oy+dy)*10 + ox+dx)*64 + c], w2[dy*3+dx], acc);
        out[((size_t)(b*HH + y0+oy)*WWW + x0+ox)*CC + c0 + c] += acc;
    }
}

// ---------------------------------------------------------------------------
extern "C" void kernel_launch(void* const* d_in, const int* in_sizes, int n_in,
                              void* d_out, int out_size) {
    const float* x_in    = (const float*)d_in[0];
    const float* illu    = (const float*)d_in[1];
    const float* prior   = (const float*)d_in[2];
    const float* wq      = (const float*)d_in[3];
    const float* wk      = (const float*)d_in[4];
    const float* wv      = (const float*)d_in[5];
    const float* rescale = (const float*)d_in[6];
    const float* wproj   = (const float*)d_in[7];
    const float* bproj   = (const float*)d_in[8];
    const float* cw1     = (const float*)d_in[9];
    const float* cw2     = (const float*)d_in[10];
    const float* pw1     = (const float*)d_in[11];
    const float* pw2     = (const float*)d_in[12];
    float* out = (float*)d_out;

    float *p_tmp, *p_cdp;
    __half *p_xh, *p_vh, *p_vih, *p_q, *p_k, *p_wt, *p_wfoldt;
    cudaGetSymbolAddress((void**)&p_xh,     g_xh);
    cudaGetSymbolAddress((void**)&p_vh,     g_vh);
    cudaGetSymbolAddress((void**)&p_vih,    g_vih);
    cudaGetSymbolAddress((void**)&p_q,      g_q);
    cudaGetSymbolAddress((void**)&p_k,      g_k);
    cudaGetSymbolAddress((void**)&p_tmp,    g_tmp);
    cudaGetSymbolAddress((void**)&p_cdp,    g_cdp);
    cudaGetSymbolAddress((void**)&p_wt,     g_wt);
    cudaGetSymbolAddress((void**)&p_wfoldt, g_wfoldt);

    cudaFuncSetAttribute(gemm_h_k<3,false,false>,
                         cudaFuncAttributeMaxDynamicSharedMemorySize, GEMM_SMEM);
    cudaFuncSetAttribute(gemm_h_k<1,true,true>,
                         cudaFuncAttributeMaxDynamicSharedMemorySize, GEMM_SMEM);
    cudaFuncSetAttribute(dwconv_fused_k,
                         cudaFuncAttributeMaxDynamicSharedMemorySize, DW_SMEM);

    zero_small_k<<<512, 256>>>();
    small_gemm_k<<<(NBATCH*2048 + 255)/256, 256>>>(prior, cw1, p_tmp, 512, 2048);
    small_gemm_k<<<(NBATCH*1024 + 255)/256, 256>>>(p_tmp, cw2, p_cdp, 2048, 1024);
    dim3 tb(32, 8), tg(16, 16, 3);
    transp3_k<<<tg, tb>>>(wq, wk, wv, p_wt);
    modulate_k<<<(MTOT*CC/4 + 255)/256, 256>>>(x_in);

    // q,k (half), vih + vh (half, fused illu) = xm @ W
    dim3 gq(12, 512);
    gemm_h_k<3,false,false><<<gq, 256, GEMM_SMEM>>>(
        p_xh, p_wt, nullptr, illu, p_q, p_k);

    gram_mma_k<<<256, 256>>>();
    softmax_k<<<32, 64>>>(rescale);
    fold_kT<<<32, 512>>>(wproj);

    // out_c = vh @ Wfold_b + bproj
    dim3 gf(4, 512);
    gemm_h_k<1,true,true><<<gf, 256, GEMM_SMEM>>>(
        p_vh, p_wfoldt, bproj, nullptr, out, nullptr);

    // PE branch fused
    dim3 cg(WWW/8, HH/8, NBATCH*8);
    dwconv_fused_k<<<cg, 256, DW_SMEM>>>(p_vih, pw1, pw2, out);
}